// round 1
// baseline (speedup 1.0000x reference)
#include <cuda_runtime.h>

#define NN 50000
#define NE 500000
#define DD 128
#define BN_EPS_F 1e-5f

// ---------------- device scratch (no allocation allowed) ----------------
__device__ float g_x[NN * DD];       // current node features
__device__ float g_agg[NN * DD];     // scatter destination
__device__ float g_h[NN * DD];       // pre-BN activations
__device__ float g_out_norm[NN];
__device__ float g_in_norm[NN];
__device__ int   g_deg[2 * NN];      // [0,NN): out-deg (src), [NN,2NN): in-deg (dst)
__device__ float g_stats[2 * DD];    // column sum, column sumsq
__device__ float g_bn[2 * DD];       // folded BN scale, shift

// ---------------- small prep kernels ----------------
__global__ void init_deg_kernel() {
    int i = blockIdx.x * 256 + threadIdx.x;
    if (i < 2 * NN) g_deg[i] = 0;
}

__global__ void count_deg_kernel(const int* __restrict__ src, const int* __restrict__ dst) {
    int e = blockIdx.x * 256 + threadIdx.x;
    if (e < NE) {
        atomicAdd(&g_deg[src[e]], 1);
        atomicAdd(&g_deg[NN + dst[e]], 1);
    }
}

__global__ void norms_kernel() {
    int i = blockIdx.x * 256 + threadIdx.x;
    if (i < NN) {
        int d0 = g_deg[i];
        int d1 = g_deg[NN + i];
        g_out_norm[i] = d0 > 0 ? rsqrtf((float)d0) : 0.f;
        g_in_norm[i]  = d1 > 0 ? rsqrtf((float)d1) : 0.f;
    }
}

// x = emb_table[node_ids]  (grid exactly NN*32 float4 threads)
__global__ void embed_kernel(const int* __restrict__ node_ids, const float* __restrict__ emb) {
    int idx = blockIdx.x * 256 + threadIdx.x;     // < NN*32
    int row = idx >> 5, c = idx & 31;
    int nid = node_ids[row];
    reinterpret_cast<float4*>(g_x)[idx] = reinterpret_cast<const float4*>(emb)[nid * 32 + c];
}

__global__ void zero_kernel() {
    int idx = blockIdx.x * 256 + threadIdx.x;     // < NN*32
    reinterpret_cast<float4*>(g_agg)[idx] = make_float4(0.f, 0.f, 0.f, 0.f);
    if (idx < 2 * DD) g_stats[idx] = 0.f;
}

// ---------------- edge scatter: agg[dst] += x[src] * out_norm[src] ----------------
// one warp per edge; each lane moves one float4 via vector reduction (REDG.128)
__global__ void scatter_kernel(const int* __restrict__ src, const int* __restrict__ dst) {
    int e = blockIdx.x * 8 + (threadIdx.x >> 5);
    if (e >= NE) return;
    int lane = threadIdx.x & 31;
    int s = src[e], d = dst[e];
    float on = g_out_norm[s];
    float4 v = *reinterpret_cast<const float4*>(&g_x[s * DD + lane * 4]);
    float* p = &g_agg[d * DD + lane * 4];
    asm volatile("red.global.add.v4.f32 [%0], {%1, %2, %3, %4};"
                 :: "l"(p), "f"(v.x * on), "f"(v.y * on), "f"(v.z * on), "f"(v.w * on)
                 : "memory");
}

// ---------------- fused dual GEMM + bias + relu + add + column stats ----------------
// h = relu((agg*in_norm) @ W + b) + relu(x @ Rw + Rb); accumulate colsum/colsumsq.
// 64-row tile per block, 256 threads, W/Rw full in smem, A/X k-major (stride 68).
#define A_STR 68
__global__ void __launch_bounds__(256, 1)
gemm_kernel(const float* __restrict__ W, const float* __restrict__ bvec,
            const float* __restrict__ Rw, const float* __restrict__ Rb) {
    extern __shared__ float sm[];
    float* sW = sm;                  // 128*128
    float* sR = sm + 16384;          // 128*128
    float* sA = sm + 32768;          // 128*68 (k-major, scaled agg)
    float* sX = sm + 41472;          // 128*68 (k-major, x)
    const int tid = threadIdx.x;
    const int base = blockIdx.x * 64;

    // stage weights
    {
        const float4* W4 = reinterpret_cast<const float4*>(W);
        const float4* R4 = reinterpret_cast<const float4*>(Rw);
        float4* sW4 = reinterpret_cast<float4*>(sW);
        float4* sR4 = reinterpret_cast<float4*>(sR);
        for (int i = tid; i < 4096; i += 256) { sW4[i] = W4[i]; sR4[i] = R4[i]; }
    }
    // stage A (agg*in_norm) and X transposed to k-major
    for (int q = tid; q < 2048; q += 256) {
        int r = q & 63;
        int kc = (q >> 6) << 2;
        int gr = base + r;
        float4 a = make_float4(0.f, 0.f, 0.f, 0.f);
        float4 xv = make_float4(0.f, 0.f, 0.f, 0.f);
        if (gr < NN) {
            float inr = g_in_norm[gr];
            a = *reinterpret_cast<const float4*>(&g_agg[gr * DD + kc]);
            a.x *= inr; a.y *= inr; a.z *= inr; a.w *= inr;
            xv = *reinterpret_cast<const float4*>(&g_x[gr * DD + kc]);
        }
        sA[(kc + 0) * A_STR + r] = a.x;  sA[(kc + 1) * A_STR + r] = a.y;
        sA[(kc + 2) * A_STR + r] = a.z;  sA[(kc + 3) * A_STR + r] = a.w;
        sX[(kc + 0) * A_STR + r] = xv.x; sX[(kc + 1) * A_STR + r] = xv.y;
        sX[(kc + 2) * A_STR + r] = xv.z; sX[(kc + 3) * A_STR + r] = xv.w;
    }
    __syncthreads();

    const int rt = tid >> 4, ct = tid & 15;
    const int r0 = rt << 2;
    float accW[4][8] = {};
    float accR[4][8] = {};

    #pragma unroll 8
    for (int k = 0; k < DD; k++) {
        float4 aA = *reinterpret_cast<const float4*>(&sA[k * A_STR + r0]);
        float4 aX = *reinterpret_cast<const float4*>(&sX[k * A_STR + r0]);
        float4 w0 = *reinterpret_cast<const float4*>(&sW[k * DD + ct * 4]);
        float4 w1 = *reinterpret_cast<const float4*>(&sW[k * DD + 64 + ct * 4]);
        float4 u0 = *reinterpret_cast<const float4*>(&sR[k * DD + ct * 4]);
        float4 u1 = *reinterpret_cast<const float4*>(&sR[k * DD + 64 + ct * 4]);
        float a_[4] = {aA.x, aA.y, aA.z, aA.w};
        float x_[4] = {aX.x, aX.y, aX.z, aX.w};
        float w_[8] = {w0.x, w0.y, w0.z, w0.w, w1.x, w1.y, w1.z, w1.w};
        float u_[8] = {u0.x, u0.y, u0.z, u0.w, u1.x, u1.y, u1.z, u1.w};
        #pragma unroll
        for (int i = 0; i < 4; i++) {
            #pragma unroll
            for (int j = 0; j < 8; j++) {
                accW[i][j] = fmaf(a_[i], w_[j], accW[i][j]);
                accR[i][j] = fmaf(x_[i], u_[j], accR[i][j]);
            }
        }
    }
    __syncthreads();

    // epilogue: bias + relu + add, write h, per-thread column partials
    float4 b0  = *reinterpret_cast<const float4*>(&bvec[ct * 4]);
    float4 b1  = *reinterpret_cast<const float4*>(&bvec[64 + ct * 4]);
    float4 rb0 = *reinterpret_cast<const float4*>(&Rb[ct * 4]);
    float4 rb1 = *reinterpret_cast<const float4*>(&Rb[64 + ct * 4]);
    float bb[8] = {b0.x, b0.y, b0.z, b0.w, b1.x, b1.y, b1.z, b1.w};
    float rr[8] = {rb0.x, rb0.y, rb0.z, rb0.w, rb1.x, rb1.y, rb1.z, rb1.w};
    float ps[8] = {};
    float pq[8] = {};
    #pragma unroll
    for (int i = 0; i < 4; i++) {
        int gr = base + r0 + i;
        if (gr < NN) {
            float hv[8];
            #pragma unroll
            for (int j = 0; j < 8; j++) {
                float h = fmaxf(accW[i][j] + bb[j], 0.f) + fmaxf(accR[i][j] + rr[j], 0.f);
                hv[j] = h;
                ps[j] += h;
                pq[j] += h * h;
            }
            *reinterpret_cast<float4*>(&g_h[gr * DD + ct * 4]) =
                make_float4(hv[0], hv[1], hv[2], hv[3]);
            *reinterpret_cast<float4*>(&g_h[gr * DD + 64 + ct * 4]) =
                make_float4(hv[4], hv[5], hv[6], hv[7]);
        }
    }
    // cross-thread column reduction via smem (reuse sA region)
    float* psums = sA;           // [16][128]
    float* qsums = sA + 2048;    // [16][128]
    *reinterpret_cast<float4*>(&psums[rt * DD + ct * 4])      = make_float4(ps[0], ps[1], ps[2], ps[3]);
    *reinterpret_cast<float4*>(&psums[rt * DD + 64 + ct * 4]) = make_float4(ps[4], ps[5], ps[6], ps[7]);
    *reinterpret_cast<float4*>(&qsums[rt * DD + ct * 4])      = make_float4(pq[0], pq[1], pq[2], pq[3]);
    *reinterpret_cast<float4*>(&qsums[rt * DD + 64 + ct * 4]) = make_float4(pq[4], pq[5], pq[6], pq[7]);
    __syncthreads();
    if (tid < DD) {
        float s = 0.f, qq = 0.f;
        #pragma unroll
        for (int t = 0; t < 16; t++) { s += psums[t * DD + tid]; qq += qsums[t * DD + tid]; }
        atomicAdd(&g_stats[tid], s);
        atomicAdd(&g_stats[DD + tid], qq);
    }
}

// ---------------- batchnorm ----------------
__global__ void bn_stats_kernel(const float* __restrict__ gamma, const float* __restrict__ beta) {
    int c = threadIdx.x;
    float mu = g_stats[c] * (1.f / NN);
    float var = g_stats[DD + c] * (1.f / NN) - mu * mu;
    var = fmaxf(var, 0.f);
    float inv = gamma[c] * rsqrtf(var + BN_EPS_F);
    g_bn[c] = inv;
    g_bn[DD + c] = beta[c] - mu * inv;
}

__global__ void bn_apply_kernel(float* __restrict__ outp) {
    int idx = blockIdx.x * 256 + threadIdx.x;   // < NN*32
    int c = (idx & 31) << 2;
    float4 h = reinterpret_cast<const float4*>(g_h)[idx];
    float4 o;
    o.x = h.x * g_bn[c + 0] + g_bn[DD + c + 0];
    o.y = h.y * g_bn[c + 1] + g_bn[DD + c + 1];
    o.z = h.z * g_bn[c + 2] + g_bn[DD + c + 2];
    o.w = h.w * g_bn[c + 3] + g_bn[DD + c + 3];
    float4* dp = outp ? reinterpret_cast<float4*>(outp) : reinterpret_cast<float4*>(g_x);
    dp[idx] = o;
}

// ---------------- launch ----------------
extern "C" void kernel_launch(void* const* d_in, const int* in_sizes, int n_in,
                              void* d_out, int out_size) {
    const int*   node_ids = (const int*)d_in[0];
    const int*   src      = (const int*)d_in[1];
    const int*   dst      = (const int*)d_in[2];
    const float* emb      = (const float*)d_in[3];
    const float* Ws       = (const float*)d_in[4];
    const float* bs       = (const float*)d_in[5];
    const float* Rws      = (const float*)d_in[6];
    const float* Rbs      = (const float*)d_in[7];
    const float* gam      = (const float*)d_in[8];
    const float* bet      = (const float*)d_in[9];
    float* outp = (float*)d_out;

    cudaFuncSetAttribute(gemm_kernel, cudaFuncAttributeMaxDynamicSharedMemorySize, 200704);

    const int NV4 = NN * DD / 4;           // 1.6M float4 elements
    init_deg_kernel<<<(2 * NN + 255) / 256, 256>>>();
    count_deg_kernel<<<(NE + 255) / 256, 256>>>(src, dst);
    norms_kernel<<<(NN + 255) / 256, 256>>>();
    embed_kernel<<<NV4 / 256, 256>>>(node_ids, emb);

    for (int l = 0; l < 3; l++) {
        zero_kernel<<<NV4 / 256, 256>>>();
        scatter_kernel<<<(NE + 7) / 8, 256>>>(src, dst);
        gemm_kernel<<<(NN + 63) / 64, 256, 200704>>>(Ws + l * DD * DD, bs + l * DD,
                                                     Rws + l * DD * DD, Rbs + l * DD);
        bn_stats_kernel<<<1, DD>>>(gam + l * DD, bet + l * DD);
        bn_apply_kernel<<<NV4 / 256, 256>>>(l == 2 ? outp : nullptr);
    }
}